// round 4
// baseline (speedup 1.0000x reference)
#include <cuda_runtime.h>
#include <cuda_bf16.h>

// DCT-II coefficients: A = 1/sqrt(8), Ck = 0.5*cos(k*pi/16)
#define CA 0.35355339059327373f
#define K1 0.4903926402016152f
#define K2 0.46193976625564337f
#define K3 0.4157348061512726f
#define K5 0.27778511650980114f
#define K6 0.19134171618254492f
#define K7 0.09754516100806417f

// invQ[kl] = 100 / LUMINANCE_QUANTIZATION_TABLE[k][l]
__constant__ float INVQ[64] = {
    100.0f/16.0f, 100.0f/11.0f, 100.0f/10.0f, 100.0f/16.0f, 100.0f/24.0f, 100.0f/40.0f,  100.0f/51.0f,  100.0f/61.0f,
    100.0f/12.0f, 100.0f/12.0f, 100.0f/14.0f, 100.0f/19.0f, 100.0f/26.0f, 100.0f/58.0f,  100.0f/60.0f,  100.0f/55.0f,
    100.0f/14.0f, 100.0f/13.0f, 100.0f/16.0f, 100.0f/24.0f, 100.0f/40.0f, 100.0f/57.0f,  100.0f/69.0f,  100.0f/56.0f,
    100.0f/14.0f, 100.0f/17.0f, 100.0f/22.0f, 100.0f/29.0f, 100.0f/51.0f, 100.0f/87.0f,  100.0f/80.0f,  100.0f/62.0f,
    100.0f/18.0f, 100.0f/22.0f, 100.0f/37.0f, 100.0f/56.0f, 100.0f/68.0f, 100.0f/109.0f, 100.0f/103.0f, 100.0f/77.0f,
    100.0f/24.0f, 100.0f/36.0f, 100.0f/55.0f, 100.0f/64.0f, 100.0f/81.0f, 100.0f/104.0f, 100.0f/113.0f, 100.0f/92.0f,
    100.0f/49.0f, 100.0f/64.0f, 100.0f/78.0f, 100.0f/87.0f, 100.0f/103.0f,100.0f/121.0f, 100.0f/120.0f, 100.0f/101.0f,
    100.0f/72.0f, 100.0f/92.0f, 100.0f/95.0f, 100.0f/98.0f, 100.0f/112.0f,100.0f/100.0f, 100.0f/103.0f, 100.0f/99.0f
};

// 8-point orthonormal DCT-II, even/odd butterfly (36 flops).
__device__ __forceinline__ void dct8(const float* __restrict__ x, float* __restrict__ y) {
    float s0 = x[0] + x[7], s1 = x[1] + x[6], s2 = x[2] + x[5], s3 = x[3] + x[4];
    float d0 = x[0] - x[7], d1 = x[1] - x[6], d2 = x[2] - x[5], d3 = x[3] - x[4];
    float e0 = s0 + s3, e1 = s1 + s2;
    float f0 = s0 - s3, f1 = s1 - s2;
    y[0] = CA * (e0 + e1);
    y[4] = CA * (e0 - e1);
    y[2] = K2 * f0 + K6 * f1;
    y[6] = K6 * f0 - K2 * f1;
    y[1] = K1 * d0 + K3 * d1 + K5 * d2 + K7 * d3;
    y[3] = K3 * d0 - K7 * d1 - K1 * d2 - K5 * d3;
    y[5] = K5 * d0 - K1 * d1 + K7 * d2 + K3 * d3;
    y[7] = K7 * d0 - K5 * d1 + K3 * d2 - K1 * d3;
}

// 8 threads per 8x8 block, 256 threads = 32 blocks per CTA.
// CTA covers (b, hb, wb0..wb0+31).  Grid = 16*128*4 = 8192 CTAs.
__global__ __launch_bounds__(256) void jpeg_dct_kernel(
    const float* __restrict__ img,   // [16, 1, 1024, 1024]
    const float* __restrict__ qf,    // [16]
    float* __restrict__ out)         // [16, 64, 128, 128]
{
    const int t   = threadIdx.x;
    const int tb  = t >> 3;          // block-in-CTA 0..31
    const int r   = t & 7;           // row within 8x8 block
    const int cta = blockIdx.x;
    const int b   = cta >> 9;
    const int hb  = (cta >> 2) & 127;
    const int wb0 = (cta & 3) << 5;

    // ---- load my row (8 floats) ----
    const float* p = img + ((size_t)b << 20) + ((size_t)hb << 13)
                         + ((size_t)r << 10) + ((wb0 + tb) << 3);
    float a[8];
    {
        float4 v0 = *reinterpret_cast<const float4*>(p);
        float4 v1 = *reinterpret_cast<const float4*>(p + 4);
        a[0] = v0.x; a[1] = v0.y; a[2] = v0.z; a[3] = v0.w;
        a[4] = v1.x; a[5] = v1.y; a[6] = v1.z; a[7] = v1.w;
    }

    // ---- row pass: d[l] = T[r][l] ----
    float d[8];
    dct8(a, d);

    // ---- 8x8 transpose across the 8-lane group via shfl.xor ----
    // After: d[i] = T[i][r]  (thread holds column l = r)
#pragma unroll
    for (int m = 1; m < 8; m <<= 1) {
        float tbuf[8];
#pragma unroll
        for (int i = 0; i < 8; i++)
            tbuf[i] = __shfl_xor_sync(0xffffffffu, d[i ^ m], m);
#pragma unroll
        for (int i = 0; i < 8; i++)
            if ((i ^ r) & m) d[i] = tbuf[i];
    }

    // ---- column pass: y[k] = Y[k][r] ----
    float y[8];
    dct8(d, y);

    // -128 centering only affects DC: Y[0][0] -= 1024 (thread r==0 owns l=0)
    if (r == 0) y[0] -= 1024.0f;

    // ---- stage to smem, XOR-swizzled (conflict-free write AND read) ----
    // addr(tb, kl) = kl*32 + (tb ^ ((kl&7)<<2))
    __shared__ float sm[2048];
#pragma unroll
    for (int k = 0; k < 8; k++)
        sm[(((k << 3) | r) << 5) + (tb ^ (r << 2))] = y[k];
    __syncthreads();

    // ---- coalesced store: warp w, lane l -> plane kl = j*8+w, wb = wb0+l ----
    const int w = t >> 5;
    const int l = t & 31;
    float q = qf[b];
    float invf = (q < 50.0f) ? (q * 2.0e-4f) : (1.0f / (200.0f - 2.0f * q));
    float* o = out + ((size_t)b << 20) + (hb << 7) + wb0 + l;
#pragma unroll
    for (int j = 0; j < 8; j++) {
        int kl = (j << 3) | w;                       // warp-uniform
        float v = sm[(kl << 5) + (l ^ (w << 2))];
        o[(size_t)kl << 14] = v * (INVQ[kl] * invf); // full 128B line per warp
    }
}

extern "C" void kernel_launch(void* const* d_in, const int* in_sizes, int n_in,
                              void* d_out, int out_size) {
    const float* img = (const float*)d_in[0];
    const float* qf  = (const float*)d_in[1];
    float* out = (float*)d_out;
    jpeg_dct_kernel<<<8192, 256>>>(img, qf, out);
}

// round 6
// speedup vs baseline: 1.5121x; 1.5121x over previous
#include <cuda_runtime.h>
#include <cuda_bf16.h>

// DCT-II coefficients: A = 1/sqrt(8), Ck = 0.5*cos(k*pi/16)
#define CA 0.35355339059327373f
#define K1 0.4903926402016152f
#define K2 0.46193976625564337f
#define K3 0.4157348061512726f
#define K5 0.27778511650980114f
#define K6 0.19134171618254492f
#define K7 0.09754516100806417f

// invQ[kl] = 100 / LUMINANCE_QUANTIZATION_TABLE[k][l]
__constant__ float INVQ[64] = {
    100.0f/16.0f, 100.0f/11.0f, 100.0f/10.0f, 100.0f/16.0f, 100.0f/24.0f, 100.0f/40.0f,  100.0f/51.0f,  100.0f/61.0f,
    100.0f/12.0f, 100.0f/12.0f, 100.0f/14.0f, 100.0f/19.0f, 100.0f/26.0f, 100.0f/58.0f,  100.0f/60.0f,  100.0f/55.0f,
    100.0f/14.0f, 100.0f/13.0f, 100.0f/16.0f, 100.0f/24.0f, 100.0f/40.0f, 100.0f/57.0f,  100.0f/69.0f,  100.0f/56.0f,
    100.0f/14.0f, 100.0f/17.0f, 100.0f/22.0f, 100.0f/29.0f, 100.0f/51.0f, 100.0f/87.0f,  100.0f/80.0f,  100.0f/62.0f,
    100.0f/18.0f, 100.0f/22.0f, 100.0f/37.0f, 100.0f/56.0f, 100.0f/68.0f, 100.0f/109.0f, 100.0f/103.0f, 100.0f/77.0f,
    100.0f/24.0f, 100.0f/36.0f, 100.0f/55.0f, 100.0f/64.0f, 100.0f/81.0f, 100.0f/104.0f, 100.0f/113.0f, 100.0f/92.0f,
    100.0f/49.0f, 100.0f/64.0f, 100.0f/78.0f, 100.0f/87.0f, 100.0f/103.0f,100.0f/121.0f, 100.0f/120.0f, 100.0f/101.0f,
    100.0f/72.0f, 100.0f/92.0f, 100.0f/95.0f, 100.0f/98.0f, 100.0f/112.0f,100.0f/100.0f, 100.0f/103.0f, 100.0f/99.0f
};

// Per-q row-transform coefficients. Thread q produces outputs for columns
// l = {0..3} (q=0) or {4..7} (q=1) in order (ya,yc,yb,yd) = l-offsets (0,1,2,3).
//   ya = CA*e0 + cA*e1            (y0 / y4)
//   yb = cb0*f0 + cb1*f1          (y2 / y6)
//   yc = cc0..3 . dd               (y1 / y5)
//   yd = cd0..3 . dd               (y3 / y7)
// where dd_j = o_j - m_j = +d_j (q=0) or -d_j (q=1); the sign flip for q=1
// is folded into the cc/cd coefficients.
__constant__ float CC[2][11] = {
  { CA,  K2,  K6,   K1,  K3,  K5,  K7,   K3, -K7, -K1, -K5},
  {-CA,  K6, -K2,  -K5,  K1, -K7, -K3,  -K7,  K5, -K3,  K1}
};

// full 8-point orthonormal DCT-II butterfly (column pass, thread-local)
__device__ __forceinline__ void dct8(const float* __restrict__ x, float* __restrict__ y) {
    float s0 = x[0] + x[7], s1 = x[1] + x[6], s2 = x[2] + x[5], s3 = x[3] + x[4];
    float d0 = x[0] - x[7], d1 = x[1] - x[6], d2 = x[2] - x[5], d3 = x[3] - x[4];
    float e0 = s0 + s3, e1 = s1 + s2;
    float f0 = s0 - s3, f1 = s1 - s2;
    y[0] = CA * (e0 + e1);
    y[4] = CA * (e0 - e1);
    y[2] = K2 * f0 + K6 * f1;
    y[6] = K6 * f0 - K2 * f1;
    y[1] = K1 * d0 + K3 * d1 + K5 * d2 + K7 * d3;
    y[3] = K3 * d0 - K7 * d1 - K1 * d2 - K5 * d3;
    y[5] = K5 * d0 - K1 * d1 + K7 * d2 + K3 * d3;
    y[7] = K7 * d0 - K5 * d1 + K3 * d2 - K1 * d3;
}

// 2 threads per 8x8 block (column halves). CTA = 256 threads = 128 blocks
// = one full (b, hb) row of blocks. Grid = 16*128 = 2048 CTAs.
// lane = tb*2 + q: loads are 512B contiguous per warp; the only cross-thread
// traffic is 4 shfl.xor(.,1) per row (mirror exchange).
__global__ __launch_bounds__(256, 4) void jpeg_dct_kernel(
    const float* __restrict__ img,   // [16, 1, 1024, 1024]
    const float* __restrict__ qf,    // [16]
    float* __restrict__ out)         // [16, 64, 128, 128]
{
    const int t  = threadIdx.x;
    const int q  = t & 1;            // column half
    const int tb = t >> 1;           // wb 0..127
    const int b  = blockIdx.x >> 7;
    const int hb = blockIdx.x & 127;

    // load my half-rows: q=0 -> cols 0..3, q=1 -> cols 4..7
    const float* p = img + ((size_t)b << 20) + ((size_t)hb << 13) + (tb << 3) + (q << 2);
    float4 X[8];
#pragma unroll
    for (int r = 0; r < 8; r++)
        X[r] = *reinterpret_cast<const float4*>(p + ((size_t)r << 10));

    // per-q coefficients (uniform within each lane-parity class)
    const float* cc = CC[q];
    const float cA  = cc[0];
    const float cb0 = cc[1], cb1 = cc[2];
    const float cc0 = cc[3], cc1 = cc[4], cc2 = cc[5], cc3 = cc[6];
    const float cd0 = cc[7], cd1 = cc[8], cd2 = cc[9], cd3 = cc[10];

    // row pass -> T[j][r] = T-matrix column (l = j + 4q), all 8 rows local
    float T[4][8];
#pragma unroll
    for (int r = 0; r < 8; r++) {
        // o_j: q=0 -> x[j]; q=1 -> x[7-j]  (branchless selects)
        float o0 = q ? X[r].w : X[r].x;
        float o1 = q ? X[r].z : X[r].y;
        float o2 = q ? X[r].y : X[r].z;
        float o3 = q ? X[r].x : X[r].w;
        // mirror exchange with partner lane
        float m0 = __shfl_xor_sync(0xffffffffu, o0, 1);
        float m1 = __shfl_xor_sync(0xffffffffu, o1, 1);
        float m2 = __shfl_xor_sync(0xffffffffu, o2, 1);
        float m3 = __shfl_xor_sync(0xffffffffu, o3, 1);
        float s0 = o0 + m0, s1 = o1 + m1, s2 = o2 + m2, s3 = o3 + m3;
        float dd0 = o0 - m0, dd1 = o1 - m1, dd2 = o2 - m2, dd3 = o3 - m3;
        float e0 = s0 + s3, e1 = s1 + s2;
        float f0 = s0 - s3, f1 = s1 - s2;
        T[0][r] = fmaf(cA, e1, CA * e0);                               // y0 / y4
        T[1][r] = fmaf(cc3, dd3, fmaf(cc2, dd2, fmaf(cc1, dd1, cc0 * dd0))); // y1 / y5
        T[2][r] = fmaf(cb1, f1, cb0 * f0);                             // y2 / y6
        T[3][r] = fmaf(cd3, dd3, fmaf(cd2, dd2, fmaf(cd1, dd1, cd0 * dd0))); // y3 / y7
    }

    // column pass: fully thread-local
    float Y[4][8];
#pragma unroll
    for (int j = 0; j < 4; j++) dct8(T[j], Y[j]);

    // -128 centering affects only the DC term Y[0][0] (owned by q==0, j==0)
    Y[0][0] -= q ? 0.0f : 1024.0f;

    // quantization scale
    float qv = qf[b];
    float invf = (qv < 50.0f) ? (qv * 2.0e-4f) : (1.0f / (200.0f - 2.0f * qv));

    // stores: plane kl = k*8 + j + 4q, offset (hb, wb=tb).
    // Base folds in 4q<<14 so all 32 offsets are compile-time immediates.
    float* o = out + ((size_t)b << 20) + ((size_t)(q << 2) << 14) + (hb << 7) + tb;
#pragma unroll
    for (int k = 0; k < 8; k++) {
#pragma unroll
        for (int j = 0; j < 4; j++) {
            int kl = (k << 3) + j + (q << 2);
            o[(size_t)((k << 3) + j) << 14] = Y[j][k] * (INVQ[kl] * invf);
        }
    }
}

extern "C" void kernel_launch(void* const* d_in, const int* in_sizes, int n_in,
                              void* d_out, int out_size) {
    const float* img = (const float*)d_in[0];
    const float* qf  = (const float*)d_in[1];
    float* out = (float*)d_out;
    jpeg_dct_kernel<<<2048, 256>>>(img, qf, out);
}